// round 11
// baseline (speedup 1.0000x reference)
#include <cuda_runtime.h>
#include <cuda_fp16.h>
#include <cstdint>

// Problem dims (fixed): X:(B,N), boundaries:(N,K+1), weight:(N,K,E), bias:(N,E)
#define BDIM 4096
#define NDIM 64
#define KDIM 128
#define EDIM 512
#define EPS_F 1e-8f
#define NCHUNK 16
#define CHK (KDIM / NCHUNK)          // 8

// Prefix table T[n][k][e] (fp16): T[n][k][e] = bias[n][e] + sum_{j<k} w[n][j][e]
// out[b][n][e] = relu( lerp(T[n][bidx], T[n][bidx+1], frac) )
__device__ __half g_T16[(size_t)NDIM * (KDIM + 1) * EDIM];
// Chunk sums: S[n][c][eg] as float4 (64*16*128 = 2MB)
__device__ float4 g_S4[(size_t)NDIM * NCHUNK * (EDIM / 4)];

#define CHUNK_THREADS (NDIM * NCHUNK * (EDIM / 4))     // 131072
#define CHUNK_BLOCKS  (CHUNK_THREADS / 256)            // 512

__device__ __forceinline__ uint2 pack4half(float4 v) {
    __half2 lo2 = __floats2half2_rn(v.x, v.y);
    __half2 hi2 = __floats2half2_rn(v.z, v.w);
    uint2 pk;
    pk.x = *(unsigned*)&lo2;
    pk.y = *(unsigned*)&hi2;
    return pk;
}

// ---------------------------------------------------------------------------
// Setup A: chunk sums only. S[n][c][eg] = sum of 8 k's (float4, coalesced).
// The binary search moved into gather (warp-ballot) — no more divergent-row
// L1tex storm.
// ---------------------------------------------------------------------------
__global__ void __launch_bounds__(256)
setup_a_kernel(const float* __restrict__ weight) {
    int t = blockIdx.x * blockDim.x + threadIdx.x;
    int eg  = t & 127;            // e = 4*eg
    int tmp = t >> 7;             // n*16 + c
    int c   = tmp & 15;
    int n   = tmp >> 4;

    const float4* wp = (const float4*)(weight + (size_t)n * KDIM * EDIM)
                     + (size_t)(c * CHK) * (EDIM / 4) + eg;

    float4 w[CHK];
#pragma unroll
    for (int j = 0; j < CHK; j++)
        w[j] = wp[(size_t)j * (EDIM / 4)];

    float4 s = w[0];
#pragma unroll
    for (int j = 1; j < CHK; j++) {
        s.x += w[j].x; s.y += w[j].y; s.z += w[j].z; s.w += w[j].w;
    }
    g_S4[t] = s;
}

// ---------------------------------------------------------------------------
// Setup B: scan. Thread = (n, c, eg). Front-batched L2-hot loads (15 chunk
// sums + 8 weights), predicated base adds, 8-step scan, packed fp16 stores.
// ---------------------------------------------------------------------------
__global__ void __launch_bounds__(256)
setup_b_kernel(const float* __restrict__ weight,
               const float* __restrict__ bias) {
    int t = blockIdx.x * blockDim.x + threadIdx.x;
    int eg  = t & 127;
    int tmp = t >> 7;
    int c   = tmp & 15;
    int n   = tmp >> 4;

    const float4* Sp = g_S4 + ((size_t)n * NCHUNK) * (EDIM / 4) + eg;
    const int k0 = c * CHK;
    const float4* wp = (const float4*)(weight + (size_t)n * KDIM * EDIM)
                     + (size_t)k0 * (EDIM / 4) + eg;

    float4 sc[NCHUNK - 1];
#pragma unroll
    for (int cc = 0; cc < NCHUNK - 1; cc++)
        sc[cc] = Sp[(size_t)cc * (EDIM / 4)];

    float4 w[CHK];
#pragma unroll
    for (int j = 0; j < CHK; j++)
        w[j] = wp[(size_t)j * (EDIM / 4)];

    float4 acc = ((const float4*)(bias + (size_t)n * EDIM))[eg];
#pragma unroll
    for (int cc = 0; cc < NCHUNK - 1; cc++) {
        if (cc < c) {
            acc.x += sc[cc].x; acc.y += sc[cc].y;
            acc.z += sc[cc].z; acc.w += sc[cc].w;
        }
    }

    uint2* Tp = (uint2*)g_T16 + ((size_t)n * (KDIM + 1) + k0) * (EDIM / 4) + eg;
#pragma unroll
    for (int j = 0; j < CHK; j++) {
        Tp[(size_t)j * (EDIM / 4)] = pack4half(acc);
        acc.x += w[j].x; acc.y += w[j].y; acc.z += w[j].z; acc.w += w[j].w;
    }
    if (c == NCHUNK - 1)
        Tp[(size_t)CHK * (EDIM / 4)] = pack4half(acc);
}

// ---------------------------------------------------------------------------
// Gather: one warp per (b,n). Warp-ballot searchsorted (4 coalesced boundary
// loads/lane + popc — O(1) depth, row L1-shared across the block), then
// front-batched table LDG.128s, fp32 lerp, STS, per-warp TMA bulk store.
// ---------------------------------------------------------------------------
__global__ void gather_kernel(const float* __restrict__ X,
                              const float* __restrict__ bnd,
                              float* __restrict__ out) {
    __shared__ float4 sm[8][EDIM / 4];                 // 8 x 2KB = 16KB

    const int lane = threadIdx.x & 31;
    const int warp = threadIdx.x >> 5;
    const int n = blockIdx.y;
    const int b = blockIdx.x * 8 + warp;

    const float x = __ldg(&X[(size_t)b * NDIM + n]);   // warp-uniform
    const float* bn = bnd + (size_t)n * (KDIM + 1);

    // lo = count(inner boundaries bn[1..127] < x), via 4 ballots
    unsigned m0 = __ballot_sync(0xFFFFFFFFu, __ldg(&bn[1 + lane]) < x);
    unsigned m1 = __ballot_sync(0xFFFFFFFFu, __ldg(&bn[33 + lane]) < x);
    unsigned m2 = __ballot_sync(0xFFFFFFFFu, __ldg(&bn[65 + lane]) < x);
    unsigned m3 = __ballot_sync(0xFFFFFFFFu,
                                (lane < 31) && (__ldg(&bn[97 + lane]) < x));
    const int lo = __popc(m0) + __popc(m1) + __popc(m2) + __popc(m3); // [0,127]

    const float s  = __ldg(&bn[lo]);                   // broadcast loads
    const float eb = __ldg(&bn[lo + 1]);
    const float frac = (x - s) / (eb - s + EPS_F);

    const uint4* T0 = (const uint4*)(g_T16 + ((size_t)n * (KDIM + 1) + lo) * EDIM);
    const uint4* T1 = T0 + (EDIM / 8);

    uint4 a0 = __ldg(&T0[lane]);
    uint4 c0 = __ldg(&T1[lane]);
    uint4 a1 = __ldg(&T0[lane + 32]);
    uint4 c1 = __ldg(&T1[lane + 32]);

#pragma unroll
    for (int j = 0; j < 2; j++) {
        const uint4& a  = j ? a1 : a0;
        const uint4& cc = j ? c1 : c0;
        const unsigned* ap = &a.x;
        const unsigned* cp = &cc.x;
        float4 r0, r1;
#pragma unroll
        for (int q = 0; q < 4; q++) {
            float2 av = __half22float2(*(const __half2*)&ap[q]);
            float2 cv = __half22float2(*(const __half2*)&cp[q]);
            float v0 = fmaxf(fmaf(frac, cv.x - av.x, av.x), 0.0f);
            float v1 = fmaxf(fmaf(frac, cv.y - av.y, av.y), 0.0f);
            if (q == 0)      { r0.x = v0; r0.y = v1; }
            else if (q == 1) { r0.z = v0; r0.w = v1; }
            else if (q == 2) { r1.x = v0; r1.y = v1; }
            else             { r1.z = v0; r1.w = v1; }
        }
        const int i = lane + 32 * j;
        sm[warp][2 * i]     = r0;
        sm[warp][2 * i + 1] = r1;
    }

    __syncwarp();

    if (lane == 0) {
        float* gdst = out + ((size_t)b * NDIM + n) * EDIM;
        uint32_t saddr;
        asm("{ .reg .u64 t; cvta.to.shared.u64 t, %1; cvt.u32.u64 %0, t; }"
            : "=r"(saddr) : "l"(&sm[warp][0]));
        asm volatile("fence.proxy.async.shared::cta;" ::: "memory");
        asm volatile(
            "cp.async.bulk.global.shared::cta.bulk_group [%0], [%1], %2;"
            :: "l"(gdst), "r"(saddr), "r"((int)(EDIM * 4)) : "memory");
        asm volatile("cp.async.bulk.commit_group;" ::: "memory");
        asm volatile("cp.async.bulk.wait_group 0;" ::: "memory");
    }
}

extern "C" void kernel_launch(void* const* d_in, const int* in_sizes, int n_in,
                              void* d_out, int out_size) {
    const float* X      = (const float*)d_in[0];   // (B, N)
    const float* bnd    = (const float*)d_in[1];   // (N, K+1)
    const float* weight = (const float*)d_in[2];   // (N, K, E)
    const float* bias   = (const float*)d_in[3];   // (N, E)
    float* out = (float*)d_out;                    // (B, N, E)

    setup_a_kernel<<<CHUNK_BLOCKS, 256>>>(weight);
    setup_b_kernel<<<CHUNK_BLOCKS, 256>>>(weight, bias);

    dim3 grid(BDIM / 8, NDIM);
    gather_kernel<<<grid, 256>>>(X, bnd, out);
}

// round 12
// speedup vs baseline: 1.0477x; 1.0477x over previous
#include <cuda_runtime.h>
#include <cuda_fp16.h>
#include <cstdint>

// Problem dims (fixed): X:(B,N), boundaries:(N,K+1), weight:(N,K,E), bias:(N,E)
#define BDIM 4096
#define NDIM 64
#define KDIM 128
#define EDIM 512
#define EPS_F 1e-8f
#define NCHUNK 16
#define CHK (KDIM / NCHUNK)          // 8
#define BROW (KDIM + 1)              // 129 floats per boundary row

// Prefix table T[n][k][e] (fp16): T[n][k][e] = bias[n][e] + sum_{j<k} w[n][j][e]
// out[b][n][e] = relu( lerp(T[n][bidx], T[n][bidx+1], frac) )
__device__ __half g_T16[(size_t)NDIM * (KDIM + 1) * EDIM];
// Per-(b,n) (frac, bidx), indexed b*N+n.
__device__ float2 g_SF[(size_t)BDIM * NDIM];

#define PREFIX_BLOCKS (NDIM * 8)                       // 512  (n x 16-wide eg slab)
#define SEARCH_BLOCKS ((BDIM * NDIM) / 256)            // 1024

__device__ __forceinline__ uint2 pack4half(float4 v) {
    __half2 lo2 = __floats2half2_rn(v.x, v.y);
    __half2 hi2 = __floats2half2_rn(v.z, v.w);
    uint2 pk;
    pk.x = *(unsigned*)&lo2;
    pk.y = *(unsigned*)&hi2;
    return pk;
}

// ---------------------------------------------------------------------------
// Setup (single launch):
//  blocks [0,512): FUSED prefix. Block = (n, 16-float4-wide e slab).
//    Thread (c, egL): front-batch 8 float4 weight loads, chunk sum -> SMEM,
//    sync, base = bias + lower chunk sums (SMEM), 8-step scan -> fp16 table.
//    One weight read total; no intermediate global buffer; no second launch.
//  blocks [512,1536): search. Stage ALL boundary rows (33KB) into SMEM, then
//    coalesced X reads + SMEM-only binary search -> g_SF. No divergent-row
//    global wavefront storm.
// ---------------------------------------------------------------------------
__global__ void __launch_bounds__(256, 2)
setup_kernel(const float* __restrict__ X,
             const float* __restrict__ bnd,
             const float* __restrict__ weight,
             const float* __restrict__ bias) {
    __shared__ float  s_bnd[NDIM * BROW];              // 33KB (search branch)
    __shared__ float4 s_csum[NCHUNK][17];              // padded (prefix branch)

    if (blockIdx.x < PREFIX_BLOCKS) {
        const int n   = blockIdx.x >> 3;
        const int egB = (blockIdx.x & 7) << 4;         // base float4-col
        const int c   = threadIdx.x >> 4;              // k-chunk 0..15
        const int egL = threadIdx.x & 15;
        const int eg  = egB + egL;                     // float4 col 0..127
        const int k0  = c * CHK;

        const float4* wp = (const float4*)(weight + (size_t)n * KDIM * EDIM)
                         + (size_t)k0 * (EDIM / 4) + eg;

        float4 w[CHK];
#pragma unroll
        for (int j = 0; j < CHK; j++)                  // front-batched MLP-8
            w[j] = wp[(size_t)j * (EDIM / 4)];

        float4 s = w[0];
#pragma unroll
        for (int j = 1; j < CHK; j++) {
            s.x += w[j].x; s.y += w[j].y; s.z += w[j].z; s.w += w[j].w;
        }
        s_csum[c][egL] = s;
        __syncthreads();

        float4 acc = ((const float4*)(bias + (size_t)n * EDIM))[eg];
#pragma unroll
        for (int cc = 0; cc < NCHUNK - 1; cc++) {
            float4 sv = s_csum[cc][egL];
            if (cc < c) {
                acc.x += sv.x; acc.y += sv.y; acc.z += sv.z; acc.w += sv.w;
            }
        }

        uint2* Tp = (uint2*)g_T16 + ((size_t)n * BROW + k0) * (EDIM / 4) + eg;
#pragma unroll
        for (int j = 0; j < CHK; j++) {
            Tp[(size_t)j * (EDIM / 4)] = pack4half(acc);
            acc.x += w[j].x; acc.y += w[j].y; acc.z += w[j].z; acc.w += w[j].w;
        }
        if (c == NCHUNK - 1)
            Tp[(size_t)CHK * (EDIM / 4)] = pack4half(acc);
    } else {
        // Stage the whole boundary table into SMEM (coalesced, L2-hot)
        for (int j = threadIdx.x; j < NDIM * BROW; j += 256)
            s_bnd[j] = bnd[j];
        __syncthreads();

        const int i = (blockIdx.x - PREFIX_BLOCKS) * 256 + threadIdx.x; // b*N+n
        const int n = i & (NDIM - 1);
        const float x = X[i];                           // fully coalesced
        const float* row = s_bnd + n * BROW;

        int lo = 0, len = KDIM - 1;                     // SMEM-only search
        while (len > 0) {
            int half = len >> 1;
            bool pred = row[1 + lo + half] < x;
            lo  += pred ? (half + 1) : 0;
            len  = pred ? (len - half - 1) : half;
        }
        const float s  = row[lo];
        const float eb = row[lo + 1];
        g_SF[i] = make_float2((x - s) / (eb - s + EPS_F), __int_as_float(lo));
    }
}

// ---------------------------------------------------------------------------
// Gather (proven 86.4us config — UNCHANGED from round 8): one warp per (b,n).
// Front-batched table LDG.128s, fp32 lerp, STS to this warp's 2KB SMEM slot,
// one per-warp cp.async.bulk TMA store. __syncwarp only.
// ---------------------------------------------------------------------------
__global__ void gather_kernel(float* __restrict__ out) {
    __shared__ float4 sm[8][EDIM / 4];                 // 8 x 2KB = 16KB

    const int lane = threadIdx.x & 31;
    const int warp = threadIdx.x >> 5;
    const int n = blockIdx.y;
    const int b = blockIdx.x * 8 + warp;

    const float2 sf = __ldg(&g_SF[(size_t)b * NDIM + n]);
    const float frac = sf.x;
    const int   lo   = __float_as_int(sf.y);

    const uint4* T0 = (const uint4*)(g_T16 + ((size_t)n * BROW + lo) * EDIM);
    const uint4* T1 = T0 + (EDIM / 8);

    uint4 a0 = __ldg(&T0[lane]);
    uint4 c0 = __ldg(&T1[lane]);
    uint4 a1 = __ldg(&T0[lane + 32]);
    uint4 c1 = __ldg(&T1[lane + 32]);

#pragma unroll
    for (int j = 0; j < 2; j++) {
        const uint4& a  = j ? a1 : a0;
        const uint4& cc = j ? c1 : c0;
        const unsigned* ap = &a.x;
        const unsigned* cp = &cc.x;
        float4 r0, r1;
#pragma unroll
        for (int q = 0; q < 4; q++) {
            float2 av = __half22float2(*(const __half2*)&ap[q]);
            float2 cv = __half22float2(*(const __half2*)&cp[q]);
            float v0 = fmaxf(fmaf(frac, cv.x - av.x, av.x), 0.0f);
            float v1 = fmaxf(fmaf(frac, cv.y - av.y, av.y), 0.0f);
            if (q == 0)      { r0.x = v0; r0.y = v1; }
            else if (q == 1) { r0.z = v0; r0.w = v1; }
            else if (q == 2) { r1.x = v0; r1.y = v1; }
            else             { r1.z = v0; r1.w = v1; }
        }
        const int i = lane + 32 * j;
        sm[warp][2 * i]     = r0;
        sm[warp][2 * i + 1] = r1;
    }

    __syncwarp();

    if (lane == 0) {
        float* gdst = out + ((size_t)b * NDIM + n) * EDIM;
        uint32_t saddr;
        asm("{ .reg .u64 t; cvta.to.shared.u64 t, %1; cvt.u32.u64 %0, t; }"
            : "=r"(saddr) : "l"(&sm[warp][0]));
        asm volatile("fence.proxy.async.shared::cta;" ::: "memory");
        asm volatile(
            "cp.async.bulk.global.shared::cta.bulk_group [%0], [%1], %2;"
            :: "l"(gdst), "r"(saddr), "r"((int)(EDIM * 4)) : "memory");
        asm volatile("cp.async.bulk.commit_group;" ::: "memory");
        asm volatile("cp.async.bulk.wait_group 0;" ::: "memory");
    }
}

extern "C" void kernel_launch(void* const* d_in, const int* in_sizes, int n_in,
                              void* d_out, int out_size) {
    const float* X      = (const float*)d_in[0];   // (B, N)
    const float* bnd    = (const float*)d_in[1];   // (N, K+1)
    const float* weight = (const float*)d_in[2];   // (N, K, E)
    const float* bias   = (const float*)d_in[3];   // (N, E)
    float* out = (float*)d_out;                    // (B, N, E)

    setup_kernel<<<PREFIX_BLOCKS + SEARCH_BLOCKS, 256>>>(X, bnd, weight, bias);

    dim3 grid(BDIM / 8, NDIM);
    gather_kernel<<<grid, 256>>>(out);
}